// round 1
// baseline (speedup 1.0000x reference)
#include <cuda_runtime.h>
#include <math.h>

// ---------------- scratch (device globals; no cudaMalloc allowed) ----------
#define B_   32
#define HW_  4096           // 64*64
#define C1O  64
#define C2O  128

__device__ float g_h1c[(size_t)B_ * HW_ * C1O];        // channel-last h1: [b][h][w][c]  (33.5 MB)
__device__ float g_off2[(size_t)B_ * 18 * HW_];        // offsets layer2 (9.4 MB)
__device__ float g_partial[(size_t)4096 * C2O];        // per-block pooled partials (2 MB)
__device__ float g_pool[B_ * C2O];                     // pooled (b,128)

// ---------------- K1: offset1 conv + deform conv1 + bn1 + relu -------------
__global__ void __launch_bounds__(128)
k1_layer1(const float* __restrict__ x,
          const float* __restrict__ ow, const float* __restrict__ ob,
          const float* __restrict__ cw, const float* __restrict__ cb,
          const float* __restrict__ g1, const float* __restrict__ be1,
          const float* __restrict__ m1, const float* __restrict__ v1)
{
    __shared__ float s_ow[486];     // 18*27
    __shared__ float s_cw[1728];    // 64*27
    __shared__ float s_ob[18];
    __shared__ float s_scale[64], s_bias[64];
    __shared__ float s_out[128 * 65];

    int tid = threadIdx.x;
    for (int i = tid; i < 486; i += 128)  s_ow[i] = ow[i];
    for (int i = tid; i < 1728; i += 128) s_cw[i] = cw[i];
    if (tid < 18) s_ob[tid] = ob[tid];
    if (tid < 64) {
        float sc = g1[tid] * rsqrtf(v1[tid] + 1e-5f);
        s_scale[tid] = sc;
        s_bias[tid]  = be1[tid] + (cb[tid] - m1[tid]) * sc;
    }
    __syncthreads();

    int lin = blockIdx.x * 128 + tid;
    int b = lin >> 12, hw = lin & 4095, h = hw >> 6, w = hw & 63;
    const float* xb = x + (size_t)b * 3 * 4096;

    // 3x3x3 window with zero pad
    float xwin[27];
    #pragma unroll
    for (int ci = 0; ci < 3; ci++)
        #pragma unroll
        for (int kh = 0; kh < 3; kh++)
            #pragma unroll
            for (int kw = 0; kw < 3; kw++) {
                int yy = h + kh - 1, xx = w + kw - 1;
                float val = 0.f;
                if (yy >= 0 && yy < 64 && xx >= 0 && xx < 64)
                    val = xb[ci * 4096 + yy * 64 + xx];
                xwin[ci * 9 + kh * 3 + kw] = val;
            }

    // 18 offsets
    float off[18];
    #pragma unroll
    for (int c = 0; c < 18; c++) {
        float a = s_ob[c];
        #pragma unroll
        for (int j = 0; j < 27; j++) a += xwin[j] * s_ow[c * 27 + j];
        off[c] = a;
    }

    // deformable sampling: v[ci*9+tap]
    float v[27];
    #pragma unroll
    for (int tap = 0; tap < 9; tap++) {
        float py = (float)(h + tap / 3 - 1) + off[tap * 2];
        float px = (float)(w + tap % 3 - 1) + off[tap * 2 + 1];
        float y0f = floorf(py), x0f = floorf(px);
        int y0 = (int)y0f, x0 = (int)x0f;
        float wy = py - y0f, wx = px - x0f;
        float w00 = (1.f - wy) * (1.f - wx), w01 = (1.f - wy) * wx;
        float w10 = wy * (1.f - wx),         w11 = wy * wx;
        bool vy0 = ((unsigned)y0 < 64u), vy1 = ((unsigned)(y0 + 1) < 64u);
        bool vx0 = ((unsigned)x0 < 64u), vx1 = ((unsigned)(x0 + 1) < 64u);
        long long i00 = (long long)y0 * 64 + x0;
        #pragma unroll
        for (int ci = 0; ci < 3; ci++) {
            const float* p = xb + ci * 4096;
            float c00 = (vy0 && vx0) ? p[i00]      : 0.f;
            float c01 = (vy0 && vx1) ? p[i00 + 1]  : 0.f;
            float c10 = (vy1 && vx0) ? p[i00 + 64] : 0.f;
            float c11 = (vy1 && vx1) ? p[i00 + 65] : 0.f;
            v[ci * 9 + tap] = c00 * w00 + c01 * w01 + c10 * w10 + c11 * w11;
        }
    }

    // 64 outputs, bn+relu, stage to smem
    #pragma unroll 4
    for (int co = 0; co < 64; co++) {
        float a = 0.f;
        #pragma unroll
        for (int j = 0; j < 27; j++) a += v[j] * s_cw[co * 27 + j];
        float val = a * s_scale[co] + s_bias[co];
        s_out[tid * 65 + co] = fmaxf(val, 0.f);
    }
    __syncthreads();

    // coalesced channel-last store
    size_t base = (size_t)blockIdx.x * 128 * 64;
    for (int i = tid; i < 8192; i += 128)
        g_h1c[base + i] = s_out[(i >> 6) * 65 + (i & 63)];
}

// ---------------- K2: offset2 conv (64 -> 18) -------------------------------
__global__ void __launch_bounds__(256)
k2_off2(const float* __restrict__ w2, const float* __restrict__ b2)
{
    __shared__ float s_w[576 * 20];   // transposed, padded: [(ci*9+pos)][o(20)]
    int tid = threadIdx.x;
    for (int i = tid; i < 18 * 576; i += 256) {
        int o = i / 576, cp = i % 576;
        s_w[cp * 20 + o] = w2[i];
    }
    for (int i = tid; i < 576; i += 256) { s_w[i * 20 + 18] = 0.f; s_w[i * 20 + 19] = 0.f; }
    __syncthreads();

    int lin = blockIdx.x * 256 + tid;
    int b = lin >> 12, hw = lin & 4095, h = hw >> 6, w = hw & 63;
    const float* hb = g_h1c + (size_t)b * HW_ * C1O;

    float acc[20];
    #pragma unroll
    for (int o = 0; o < 20; o++) acc[o] = 0.f;

    #pragma unroll
    for (int pos = 0; pos < 9; pos++) {
        int kh = pos / 3, kw = pos % 3;
        int yy = h + kh - 1, xx = w + kw - 1;
        bool valid = (yy >= 0 && yy < 64 && xx >= 0 && xx < 64);
        const float4* vp = (const float4*)(hb + (size_t)(yy * 64 + xx) * 64);
        #pragma unroll 1
        for (int c4 = 0; c4 < 16; c4++) {
            float4 v4 = valid ? vp[c4] : make_float4(0.f, 0.f, 0.f, 0.f);
            float vv[4] = {v4.x, v4.y, v4.z, v4.w};
            #pragma unroll
            for (int j = 0; j < 4; j++) {
                const float* wb = &s_w[((c4 * 4 + j) * 9 + pos) * 20];
                #pragma unroll
                for (int o = 0; o < 20; o += 4) {
                    float4 wq = *(const float4*)(wb + o);
                    acc[o]     += vv[j] * wq.x;
                    acc[o + 1] += vv[j] * wq.y;
                    acc[o + 2] += vv[j] * wq.z;
                    acc[o + 3] += vv[j] * wq.w;
                }
            }
        }
    }
    #pragma unroll
    for (int o = 0; o < 18; o++)
        g_off2[(size_t)(b * 18 + o) * HW_ + hw] = acc[o] + b2[o];
}

// ---------------- K3: deform conv2 + bn2 + relu + pooled partials ----------
// block: (b, h, wtile of 32 locs); 256 threads; dynamic smem.
#define K3_SMEM_WORDS (32*577 + 128*33 + 288 + 288 + 288 + 288 + 128 + 128)
#define K3_SMEM_BYTES (K3_SMEM_WORDS * 4)

__global__ void __launch_bounds__(256)
k3_deform2(const float* __restrict__ cw, const float* __restrict__ cb,
           const float* __restrict__ g2, const float* __restrict__ be2,
           const float* __restrict__ m2, const float* __restrict__ v2)
{
    extern __shared__ float smem[];
    float* v_s     = smem;                  // [loc][e] padded: loc*577+e
    float* s_wt    = v_s + 32 * 577;        // [co][e_l] padded: co*33+e_l
    float* s_wy    = s_wt + 128 * 33;       // 288
    float* s_wx    = s_wy + 288;            // 288
    int*   s_y0    = (int*)(s_wx + 288);    // 288
    int*   s_x0    = s_y0 + 288;            // 288
    float* s_scale = (float*)(s_x0 + 288);  // 128
    float* s_bias  = s_scale + 128;         // 128

    int tid = threadIdx.x;
    int blk = blockIdx.x;
    int wt = blk & 1, h = (blk >> 1) & 63, b = blk >> 7;
    int w0 = wt * 32;

    if (tid < 128) {
        float sc = g2[tid] * rsqrtf(v2[tid] + 1e-5f);
        s_scale[tid] = sc;
        s_bias[tid]  = be2[tid] + (cb[tid] - m2[tid]) * sc;
    }
    // phase A: offsets -> sampling coords
    for (int t = tid; t < 288; t += 256) {
        int tap = t >> 5, loc = t & 31;
        int w = w0 + loc;
        float dy = g_off2[(size_t)(b * 18 + tap * 2)     * HW_ + h * 64 + w];
        float dx = g_off2[(size_t)(b * 18 + tap * 2 + 1) * HW_ + h * 64 + w];
        float py = (float)(h + tap / 3 - 1) + dy;
        float px = (float)(w + tap % 3 - 1) + dx;
        float y0f = floorf(py), x0f = floorf(px);
        s_y0[t] = (int)y0f; s_x0[t] = (int)x0f;
        s_wy[t] = py - y0f; s_wx[t] = px - x0f;
    }
    __syncthreads();

    // phase B: bilinear sampling, channel-last vectorized
    const float* hb = g_h1c + (size_t)b * HW_ * C1O;
    for (int st = tid; st < 4608; st += 256) {          // 288 tasks x 16 ci-chunks
        int task = st >> 4, t16 = st & 15;
        int tap = task >> 5, loc = task & 31;
        int y0 = s_y0[task], x0 = s_x0[task];
        float wy = s_wy[task], wx = s_wx[task];
        float w00 = (1.f - wy) * (1.f - wx), w01 = (1.f - wy) * wx;
        float w10 = wy * (1.f - wx),          w11 = wy * wx;
        bool vy0 = ((unsigned)y0 < 64u), vy1 = ((unsigned)(y0 + 1) < 64u);
        bool vx0 = ((unsigned)x0 < 64u), vx1 = ((unsigned)(x0 + 1) < 64u);
        int ci = t16 * 4;
        float4 z = make_float4(0.f, 0.f, 0.f, 0.f);
        const float* p00 = hb + ((long long)y0 * 64 + x0) * 64 + ci;
        float4 c00 = (vy0 && vx0) ? *(const float4*)(p00)            : z;
        float4 c01 = (vy0 && vx1) ? *(const float4*)(p00 + 64)       : z;
        float4 c10 = (vy1 && vx0) ? *(const float4*)(p00 + 4096)     : z;
        float4 c11 = (vy1 && vx1) ? *(const float4*)(p00 + 4096 + 64): z;
        float* vd = &v_s[loc * 577 + ci * 9 + tap];
        vd[0]  = c00.x * w00 + c01.x * w01 + c10.x * w10 + c11.x * w11;
        vd[9]  = c00.y * w00 + c01.y * w01 + c10.y * w10 + c11.y * w11;
        vd[18] = c00.z * w00 + c01.z * w01 + c10.z * w10 + c11.z * w11;
        vd[27] = c00.w * w00 + c01.w * w01 + c10.w * w10 + c11.w * w11;
    }
    __syncthreads();

    // phase C: GEMM 128co x 32loc, dot length 576; 4x4 register tile / thread
    int lw = tid & 7, cg = tid >> 3;
    float acc[4][4];
    #pragma unroll
    for (int r = 0; r < 4; r++)
        #pragma unroll
        for (int j = 0; j < 4; j++) acc[r][j] = 0.f;

    for (int et = 0; et < 18; et++) {
        #pragma unroll
        for (int k = 0; k < 16; k++) {
            int idx = tid + k * 256;                  // 0..4095
            int e_l = idx & 31, co = idx >> 5;
            s_wt[co * 33 + e_l] = cw[co * 576 + et * 32 + e_l];
        }
        __syncthreads();
        #pragma unroll 4
        for (int e_l = 0; e_l < 32; e_l++) {
            int e = et * 32 + e_l;
            float vv[4], ww[4];
            #pragma unroll
            for (int j = 0; j < 4; j++) vv[j] = v_s[(lw * 4 + j) * 577 + e];
            #pragma unroll
            for (int r = 0; r < 4; r++) ww[r] = s_wt[(cg + 32 * r) * 33 + e_l];
            #pragma unroll
            for (int r = 0; r < 4; r++)
                #pragma unroll
                for (int j = 0; j < 4; j++) acc[r][j] += ww[r] * vv[j];
        }
        __syncthreads();
    }

    // epilogue: bn + relu + partial pooled sum (deterministic)
    #pragma unroll
    for (int r = 0; r < 4; r++) {
        int co = cg + 32 * r;
        float sc = s_scale[co], bi = s_bias[co];
        float lsum = 0.f;
        #pragma unroll
        for (int j = 0; j < 4; j++)
            lsum += fmaxf(acc[r][j] * sc + bi, 0.f);
        lsum += __shfl_xor_sync(0xffffffffu, lsum, 1);
        lsum += __shfl_xor_sync(0xffffffffu, lsum, 2);
        lsum += __shfl_xor_sync(0xffffffffu, lsum, 4);
        if (lw == 0) g_partial[(size_t)blk * 128 + co] = lsum;
    }
}

// ---------------- K3b: reduce partials -> pooled ----------------------------
__global__ void k3b_reduce()
{
    int idx = blockIdx.x * 256 + threadIdx.x;
    if (idx >= B_ * C2O) return;
    int b = idx >> 7, co = idx & 127;
    float s = 0.f;
    for (int i = 0; i < 128; i++)
        s += g_partial[(size_t)(b * 128 + i) * 128 + co];
    g_pool[idx] = s * (1.f / 4096.f);
}

// ---------------- K4: fc1 + relu + fc2 --------------------------------------
__global__ void __launch_bounds__(256)
k4_fc(const float* __restrict__ fc1w, const float* __restrict__ fc1b,
      const float* __restrict__ fc2w, const float* __restrict__ fc2b,
      float* __restrict__ out)
{
    __shared__ float sp[128];
    __shared__ float hid[256];
    int b = blockIdx.x, tid = threadIdx.x;
    if (tid < 128) sp[tid] = g_pool[b * 128 + tid];
    __syncthreads();
    {
        float a = fc1b[tid];
        #pragma unroll 8
        for (int j = 0; j < 128; j++) a += fc1w[tid * 128 + j] * sp[j];
        hid[tid] = fmaxf(a, 0.f);
    }
    __syncthreads();
    if (tid < 200) {
        float a = fc2b[tid];
        #pragma unroll 8
        for (int j = 0; j < 256; j++) a += fc2w[tid * 256 + j] * hid[j];
        out[b * 200 + tid] = a;
    }
}

// ---------------- launch -----------------------------------------------------
extern "C" void kernel_launch(void* const* d_in, const int* in_sizes, int n_in,
                              void* d_out, int out_size)
{
    const float* x    = (const float*)d_in[0];
    const float* o1w  = (const float*)d_in[1];
    const float* o1b  = (const float*)d_in[2];
    const float* c1w  = (const float*)d_in[3];
    const float* c1b  = (const float*)d_in[4];
    const float* g1   = (const float*)d_in[5];
    const float* be1  = (const float*)d_in[6];
    const float* m1   = (const float*)d_in[7];
    const float* v1   = (const float*)d_in[8];
    const float* o2w  = (const float*)d_in[9];
    const float* o2b  = (const float*)d_in[10];
    const float* c2w  = (const float*)d_in[11];
    const float* c2b  = (const float*)d_in[12];
    const float* g2   = (const float*)d_in[13];
    const float* be2  = (const float*)d_in[14];
    const float* m2   = (const float*)d_in[15];
    const float* v2   = (const float*)d_in[16];
    const float* f1w  = (const float*)d_in[17];
    const float* f1b  = (const float*)d_in[18];
    const float* f2w  = (const float*)d_in[19];
    const float* f2b  = (const float*)d_in[20];
    float* out = (float*)d_out;

    cudaFuncSetAttribute(k3_deform2, cudaFuncAttributeMaxDynamicSharedMemorySize, K3_SMEM_BYTES);

    k1_layer1<<<1024, 128>>>(x, o1w, o1b, c1w, c1b, g1, be1, m1, v1);
    k2_off2<<<512, 256>>>(o2w, o2b);
    k3_deform2<<<4096, 256, K3_SMEM_BYTES>>>(c2w, c2b, g2, be2, m2, v2);
    k3b_reduce<<<16, 256>>>();
    k4_fc<<<32, 256>>>(f1w, f1b, f2w, f2b, out);
}